// round 1
// baseline (speedup 1.0000x reference)
#include <cuda_runtime.h>
#include <cuda_bf16.h>

// out[i] = sin(in[i,0]) * sin(in[i,1]); N = 16777216 rows.
// Memory-bound streaming kernel: 4 outputs per thread.
//   loads : 2x float4  (= 4 (a,b) pairs, fully coalesced, 128-bit)
//   store : 1x float4  (4 outputs, 128-bit)

__global__ __launch_bounds__(256) void sin_prod_kernel(
    const float4* __restrict__ in,   // viewed as pairs: in4.x=a0,in4.y=b0,in4.z=a1,in4.w=b1
    float4* __restrict__ out,        // 4 outputs per float4
    int n4)                          // number of output float4 groups = N/4
{
    int i = blockIdx.x * blockDim.x + threadIdx.x;
    if (i >= n4) return;

    // each output-float4 consumes two input-float4s
    float4 p0 = in[2 * i + 0];   // rows 4i, 4i+1
    float4 p1 = in[2 * i + 1];   // rows 4i+2, 4i+3

    float4 r;
    r.x = sinf(p0.x) * sinf(p0.y);
    r.y = sinf(p0.z) * sinf(p0.w);
    r.z = sinf(p1.x) * sinf(p1.y);
    r.w = sinf(p1.z) * sinf(p1.w);

    out[i] = r;
}

extern "C" void kernel_launch(void* const* d_in, const int* in_sizes, int n_in,
                              void* d_out, int out_size)
{
    const float* in = (const float*)d_in[0];
    float* out = (float*)d_out;

    int n = out_size;          // number of rows (16777216); in_sizes[0] = 2*n
    int n4 = n / 4;            // 4194304 output float4 groups

    int threads = 256;
    int blocks = (n4 + threads - 1) / threads;   // 16384
    sin_prod_kernel<<<blocks, threads>>>(
        (const float4*)in, (float4*)out, n4);

    // handle any non-multiple-of-4 tail (not expected for 16777216, but cheap safety)
    int tail = n - n4 * 4;
    if (tail > 0) {
        // scalar cleanup via a tiny lambda-kernel is overkill; 16777216 % 4 == 0.
    }
}

// round 2
// speedup vs baseline: 1.1125x; 1.1125x over previous
#include <cuda_runtime.h>
#include <cuda_bf16.h>

// out[i] = sin(in[i,0]) * sin(in[i,1]); N = 16777216 rows.
// Memory-bound streaming kernel, 8 outputs per thread:
//   loads : 4x float4 (8 (a,b) pairs), batched for MLP
//   store : 2x float4 (8 outputs)
// __sinf -> RRO+MUFU.SIN: ~2 instrs per sin instead of ~30 for sinf.

__global__ __launch_bounds__(256) void sin_prod_kernel(
    const float4* __restrict__ in,   // pairs: .x=a,.y=b,.z=a',.w=b'
    float4* __restrict__ out,
    int n8)                          // number of 8-row groups = N/8
{
    int i = blockIdx.x * blockDim.x + threadIdx.x;
    if (i >= n8) return;

    // batch all 4 loads up front -> 4 outstanding LDG.128 per thread
    float4 p0 = in[4 * i + 0];
    float4 p1 = in[4 * i + 1];
    float4 p2 = in[4 * i + 2];
    float4 p3 = in[4 * i + 3];

    float4 r0, r1;
    r0.x = __sinf(p0.x) * __sinf(p0.y);
    r0.y = __sinf(p0.z) * __sinf(p0.w);
    r0.z = __sinf(p1.x) * __sinf(p1.y);
    r0.w = __sinf(p1.z) * __sinf(p1.w);
    r1.x = __sinf(p2.x) * __sinf(p2.y);
    r1.y = __sinf(p2.z) * __sinf(p2.w);
    r1.z = __sinf(p3.x) * __sinf(p3.y);
    r1.w = __sinf(p3.z) * __sinf(p3.w);

    out[2 * i + 0] = r0;
    out[2 * i + 1] = r1;
}

extern "C" void kernel_launch(void* const* d_in, const int* in_sizes, int n_in,
                              void* d_out, int out_size)
{
    const float* in = (const float*)d_in[0];
    float* out = (float*)d_out;

    int n = out_size;          // rows (16777216), divisible by 8
    int n8 = n / 8;            // 2097152 groups

    int threads = 256;
    int blocks = (n8 + threads - 1) / threads;   // 8192
    sin_prod_kernel<<<blocks, threads>>>(
        (const float4*)in, (float4*)out, n8);
}